// round 15
// baseline (speedup 1.0000x reference)
#include <cuda_runtime.h>
#include <cuda_bf16.h>

#define NB 64
#define C  64
#define T  256
#define V  25
#define S  3
#define R  8
#define O  64

typedef unsigned long long ull;
typedef unsigned int u32;

// ---------------- scratch ----------------
__device__ float  g_xm[NB * C * V];
__device__ __nv_bfloat16 g_w3h[S * O * C];               // w3 hi, rows [s*64+o][c]
__device__ __nv_bfloat16 g_w3l[S * O * C];               // w3 lo
__device__ float  g_R4[(size_t)S * NB * O * V * V];
__device__ float  g_x3[(size_t)S * NB * O * T * V];      // fp32
__device__ float2 g_stats[O];
__device__ float2 g_part2[O * NB];

// ---------------- f32x2 helpers (k_y) ----------------
__device__ __forceinline__ ull pk(float lo, float hi) {
    ull r; asm("mov.b64 %0, {%1,%2};" : "=l"(r) : "f"(lo), "f"(hi)); return r;
}
__device__ __forceinline__ void upk(float& lo, float& hi, ull v) {
    asm("mov.b64 {%0,%1}, %2;" : "=f"(lo), "=f"(hi) : "l"(v));
}
__device__ __forceinline__ ull f2fma(ull a, ull b, ull c) {
    ull d; asm("fma.rn.f32x2 %0, %1, %2, %3;" : "=l"(d) : "l"(a), "l"(b), "l"(c)); return d;
}

// ---------------- warp-MMA helpers (sm_80+ PTX) ----------------
__device__ __forceinline__ u32 s2u(const void* p) {
    u32 a; asm("{ .reg .u64 t; cvta.to.shared.u64 t, %1; cvt.u32.u64 %0, t; }" : "=r"(a) : "l"(p));
    return a;
}
__device__ __forceinline__ u32 sw128(u32 b) { return b ^ ((b >> 3) & 0x70); }

__device__ __forceinline__ void ldsm_x4(u32* r, u32 addr) {
    asm volatile("ldmatrix.sync.aligned.m8n8.x4.shared.b16 {%0,%1,%2,%3}, [%4];"
        : "=r"(r[0]), "=r"(r[1]), "=r"(r[2]), "=r"(r[3]) : "r"(addr));
}
__device__ __forceinline__ void ldsm_x4_t(u32* r, u32 addr) {
    asm volatile("ldmatrix.sync.aligned.m8n8.x4.trans.shared.b16 {%0,%1,%2,%3}, [%4];"
        : "=r"(r[0]), "=r"(r[1]), "=r"(r[2]), "=r"(r[3]) : "r"(addr));
}
__device__ __forceinline__ void mma16816(float* d, const u32* a, u32 b0, u32 b1) {
    asm volatile(
        "mma.sync.aligned.m16n8k16.row.col.f32.bf16.bf16.f32 "
        "{%0,%1,%2,%3}, {%4,%5,%6,%7}, {%8,%9}, {%0,%1,%2,%3};"
        : "+f"(d[0]), "+f"(d[1]), "+f"(d[2]), "+f"(d[3])
        : "r"(a[0]), "r"(a[1]), "r"(a[2]), "r"(a[3]), "r"(b0), "r"(b1));
}

// ---------------- K0: w3 -> bf16 hi/lo (layout already [s][o][c]) ----------------
__global__ void k_wb(const float* __restrict__ w3g) {
    int i = blockIdx.x * 256 + threadIdx.x;
    float w = w3g[i];
    __nv_bfloat16 h = __float2bfloat16(w);
    g_w3h[i] = h;
    g_w3l[i] = __float2bfloat16(w - __bfloat162float(h));
}

// ---------------- K1: xm[n,c,v] = mean_t x ----------------
__global__ void k_xm(const float* __restrict__ x) {
    __shared__ float red[256 * V];
    int bx  = blockIdx.x;
    int tid = threadIdx.x;
    const float* row = x + (size_t)bx * T * V + (size_t)tid * V;
    #pragma unroll
    for (int v = 0; v < V; ++v) red[tid * V + v] = row[v];
    __syncthreads();
    for (int st = 128; st > 0; st >>= 1) {
        if (tid < st) {
            #pragma unroll
            for (int v = 0; v < V; ++v) red[tid * V + v] += red[(tid + st) * V + v];
        }
        __syncthreads();
    }
    if (tid < V) g_xm[bx * V + tid] = red[tid] * (1.0f / T);
}

// ---------------- K2: x3 GEMM, split-bf16 3-term, fused x conversion (R12 form) ----------------
constexpr int SM_AH = 0;        // 24576
constexpr int SM_AL = 24576;    // 24576
constexpr int SM_BH = 49152;    // 8192
constexpr int SM_BL = 57344;    // 8192
constexpr int SM_TOT = 65536;

__global__ void __launch_bounds__(384) k_x3m(const float* __restrict__ x,
                                             const float* __restrict__ b3g)
{
    extern __shared__ char smc[];
    int tid = threadIdx.x, wid = tid >> 5, lane = tid & 31;
    int n = blockIdx.y, tv0 = blockIdx.x * 64;

    // A tiles (w3 hi/lo bf16), swizzled: 192 rows x 128B each
    for (int i = tid; i < 2 * 192 * 8; i += 384) {
        int half = i >= 1536;
        int j = half ? (i - 1536) : i;
        int row = j >> 3, off = (j & 7) * 16;
        const char* src = reinterpret_cast<const char*>(half ? g_w3l : g_w3h);
        uint4 v = *reinterpret_cast<const uint4*>(src + row * 128 + off);
        *reinterpret_cast<uint4*>(smc + (half ? SM_AL : SM_AH) + sw128(row * 128 + off)) = v;
    }
    // B tiles: read x fp32, convert to hi/lo bf16 in-flight
    for (int i = tid; i < 64 * 32; i += 384) {
        int c = i >> 5, j2 = i & 31;
        float2 v = *reinterpret_cast<const float2*>(
            x + ((size_t)(n * C + c)) * 6400 + tv0 + j2 * 2);
        __nv_bfloat16 h0 = __float2bfloat16(v.x), h1 = __float2bfloat16(v.y);
        __nv_bfloat16 l0 = __float2bfloat16(v.x - __bfloat162float(h0));
        __nv_bfloat16 l1 = __float2bfloat16(v.y - __bfloat162float(h1));
        u32 off = sw128((u32)(c * 128 + j2 * 4));
        *reinterpret_cast<__nv_bfloat162*>(smc + SM_BH + off) = __nv_bfloat162(h0, h1);
        *reinterpret_cast<__nv_bfloat162*>(smc + SM_BL + off) = __nv_bfloat162(l0, l1);
    }
    __syncthreads();

    u32 sah = s2u(smc + SM_AH), sal = s2u(smc + SM_AL);
    u32 sbh = s2u(smc + SM_BH), sbl = s2u(smc + SM_BL);
    int gid = lane >> 2, tig = lane & 3;
    int m0 = wid * 16;

    float acc[8][4];
    #pragma unroll
    for (int j = 0; j < 8; ++j)
        #pragma unroll
        for (int q = 0; q < 4; ++q) acc[j][q] = 0.f;

    #pragma unroll
    for (int k0 = 0; k0 < 64; k0 += 16) {
        u32 arow = sw128((m0 + (lane & 15)) * 128 + (lane >> 4) * 16 + k0 * 2);
        u32 ah[4], al[4];
        ldsm_x4(ah, sah + arow);
        ldsm_x4(al, sal + arow);
        int krow = k0 + (lane & 7) + ((lane >> 3) & 1) * 8;
        u32 bh[4][4], bl[4][4];
        #pragma unroll
        for (int nt = 0; nt < 4; ++nt) {
            u32 boff = sw128(krow * 128 + nt * 32 + (lane >> 4) * 16);
            ldsm_x4_t(bh[nt], sbh + boff);
            ldsm_x4_t(bl[nt], sbl + boff);
        }
        #pragma unroll
        for (int nt = 0; nt < 4; ++nt) {
            mma16816(acc[2 * nt],     ah, bh[nt][0], bh[nt][1]);
            mma16816(acc[2 * nt + 1], ah, bh[nt][2], bh[nt][3]);
            mma16816(acc[2 * nt],     ah, bl[nt][0], bl[nt][1]);
            mma16816(acc[2 * nt + 1], ah, bl[nt][2], bl[nt][3]);
            mma16816(acc[2 * nt],     al, bh[nt][0], bh[nt][1]);
            mma16816(acc[2 * nt + 1], al, bh[nt][2], bh[nt][3]);
        }
    }

    // bias + store (D rows m = s*64 + o)
    int s = wid >> 2;
    int o0 = (wid & 3) * 16 + gid;
    float bias0 = b3g[s * O + o0];
    float bias1 = b3g[s * O + o0 + 8];
    float* d0 = g_x3 + (((size_t)s * NB + n) * O + o0) * 6400 + tv0;
    float* d1 = d0 + (size_t)8 * 6400;
    #pragma unroll
    for (int j = 0; j < 8; ++j) {
        int col = j * 8 + 2 * tig;
        *reinterpret_cast<float2*>(d0 + col) =
            make_float2(acc[j][0] + bias0, acc[j][1] + bias0);
        *reinterpret_cast<float2*>(d1 + col) =
            make_float2(acc[j][2] + bias1, acc[j][3] + bias1);
    }
}

// ---------------- K3: build scalar R4 ----------------
__global__ void k_R(const float* __restrict__ Ag,   const float* __restrict__ alphag,
                    const float* __restrict__ w1g,  const float* __restrict__ b1g,
                    const float* __restrict__ w2g,  const float* __restrict__ b2g,
                    const float* __restrict__ w4g,  const float* __restrict__ b4g,
                    const float* __restrict__ pw1g, const float* __restrict__ pb1g,
                    const float* __restrict__ pw2g, const float* __restrict__ pb2g,
                    const float* __restrict__ dwwg, const float* __restrict__ pjwg,
                    const float* __restrict__ betag,const float* __restrict__ gammag)
{
    extern __shared__ float sm[];
    float* q1s = sm;            // 5000 (reused as ta)
    float* qas = sm + 5000;     // 5000
    float* ds  = sm + 10000;    // 5000
    float* x1s = sm + 15000;    // 200
    float* x2s = sm + 15200;    // 200
    float* as_ = sm + 15400;    // 200
    float* bs_ = sm + 15600;    // 200

    int n = blockIdx.x, s = blockIdx.y;
    int tid = threadIdx.x;
    const float* xm = g_xm + n * (C * V);

    for (int idx = tid; idx < R * V; idx += blockDim.x) {
        int r = idx / V, u = idx % V;
        float s1 = b1g[s * R + r], s2 = b2g[s * R + r];
        const float* w1r = w1g + (s * R + r) * C;
        const float* w2r = w2g + (s * R + r) * C;
        for (int c = 0; c < C; ++c) {
            float xv = xm[c * V + u];
            s1 = fmaf(w1r[c], xv, s1);
            s2 = fmaf(w2r[c], xv, s2);
        }
        x1s[idx] = s1; x2s[idx] = s2;
    }
    __syncthreads();
    for (int idx = tid; idx < R * V; idx += blockDim.x) {
        int r = idx / V, u = idx % V;
        const float* p1 = pw1g + (s * R + r) * (2 * R);
        float av = 0.f, bv = 0.f;
        #pragma unroll
        for (int p = 0; p < R; ++p) {
            av = fmaf(p1[p],     x2s[p * V + u], av);
            bv = fmaf(p1[R + p], x2s[p * V + u], bv);
        }
        as_[idx] = av; bs_[idx] = bv;
    }
    __syncthreads();
    for (int idx = tid; idx < R * V * V; idx += blockDim.x) {
        int r = idx / (V * V), uv = idx % (V * V), u = uv / V, v = uv % V;
        q1s[idx] = tanhf(x1s[r * V + u] - x2s[r * V + v]);
    }
    __syncthreads();
    float gma = gammag[s];
    for (int uv = tid; uv < V * V; uv += blockDim.x) {
        int u = uv / V, v = uv % V;
        float h[R];
        #pragma unroll
        for (int p = 0; p < R; ++p)
            h[p] = fmaxf(as_[p * V + u] + bs_[p * V + v] + pb1g[s * R + p], 0.f);
        #pragma unroll
        for (int r = 0; r < R; ++r) {
            float q2 = pb2g[s * R + r];
            const float* p2 = pw2g + (s * R + r) * R;
            #pragma unroll
            for (int p = 0; p < R; ++p) q2 = fmaf(p2[p], h[p], q2);
            qas[r * V * V + uv] = q1s[r * V * V + uv] + gma * q2;
        }
    }
    __syncthreads();
    for (int idx = tid; idx < R * V * V; idx += blockDim.x) {
        int r = idx / (V * V), uv = idx % (V * V), u = uv / V, v = uv % V;
        const float* kw = dwwg + (s * R + r) * 9;
        float acc = 0.f;
        #pragma unroll
        for (int ki = 0; ki < 3; ++ki) {
            int uu = u + ki - 1; if (uu < 0 || uu >= V) continue;
            #pragma unroll
            for (int kj = 0; kj < 3; ++kj) {
                int vv = v + kj - 1; if (vv < 0 || vv >= V) continue;
                acc = fmaf(q1s[r * V * V + uu * V + vv], kw[ki * 3 + kj], acc);
            }
        }
        ds[idx] = acc;
    }
    __syncthreads();
    for (int idx = tid; idx < R * V * V; idx += blockDim.x) {
        int r = idx / (V * V), uv = idx % (V * V), u = uv / V, v = uv % V;
        float acc = 0.f;
        for (int ki = -1; ki <= 1; ++ki) {
            int uu = u + ki; if (uu < 0 || uu >= V) continue;
            for (int kj = -1; kj <= 1; ++kj) {
                int vv = v + kj; if (vv < 0 || vv >= V) continue;
                acc += ds[r * V * V + uu * V + vv];
            }
        }
        q1s[idx] = tanhf(acc * (1.f / 9.f));
    }
    __syncthreads();
    float alpha = alphag[0], beta = betag[s];
    const float* ta = q1s;
    float* dst = g_R4 + ((size_t)(s * NB + n)) * O * 625;
    for (int idx = tid; idx < O * 625; idx += blockDim.x) {
        int o = idx / 625, uv = idx % 625;
        float a1 = b4g[s * O + o], a2 = 0.f;
        const float* w4r = w4g + (s * O + o) * R;
        const float* pjr = pjwg + (s * O + o) * R;
        #pragma unroll
        for (int r = 0; r < R; ++r) {
            a1 = fmaf(w4r[r], qas[r * V * V + uv], a1);
            a2 = fmaf(pjr[r], ta[r * V * V + uv], a2);
        }
        dst[idx] = fmaf(alpha, a1, Ag[s * V * V + uv]) + beta * a2;
    }
}

// ---------------- K4: y = R-contraction, 4t/thread, dup-R ull smem, fused BN partials ----------------
// smem: xs 6400 f | Rd 2100 ull (3 x 25 x 28 dup) | rs 64 | rq 64
constexpr int KY_SMEM_B = 6400 * 4 + 2100 * 8 + 128 * 4;   // 25600+16800+512 = 42912

__global__ void __launch_bounds__(64) k_y(float* __restrict__ ybuf)
{
    extern __shared__ float smf[];
    float* xs = smf;                                         // 6400 floats
    ull*   Rd = reinterpret_cast<ull*>(smf + 6400);          // 2100 ull
    float* rs = smf + 6400 + 4200;                           // 64
    float* rq = rs + 64;                                     // 64
    int n = blockIdx.y, o = blockIdx.x;
    int tid = threadIdx.x;      // t quad = {tid, tid+64, tid+128, tid+192}

    // stage R duplicated: Rd[s*700 + u*28 + j] = pk(r, r), zero-padded j>=25
    for (int i = tid; i < S * 25 * 28; i += 64) {
        int s = i / 700, rem = i % 700, u = rem / 28, j = rem % 28;
        float rv = (j < 25) ? g_R4[(((size_t)s * NB + n) * O + o) * 625 + u * 25 + j] : 0.f;
        Rd[i] = pk(rv, rv);
    }

    ull acc[25][2];
    #pragma unroll
    for (int u = 0; u < 25; ++u) { acc[u][0] = 0ull; acc[u][1] = 0ull; }

    #pragma unroll 1
    for (int s = 0; s < S; ++s) {
        __syncthreads();
        {
            const float4* src = reinterpret_cast<const float4*>(
                g_x3 + (((size_t)(s * NB + n)) * O + o) * 6400);
            float4* dst = reinterpret_cast<float4*>(xs);
            for (int i = tid; i < 1600; i += 64) dst[i] = src[i];
        }
        __syncthreads();
        const ull* Rp = Rd + s * 700;
        #pragma unroll 1
        for (int vg = 0; vg < 6; ++vg) {
            ull xq[4][2];
            #pragma unroll
            for (int vv = 0; vv < 4; ++vv) {
                int v = vg * 4 + vv;
                float a0 = xs[tid * 25 + v];
                float a1 = xs[(tid + 64) * 25 + v];
                float a2 = xs[(tid + 128) * 25 + v];
                float a3 = xs[(tid + 192) * 25 + v];
                xq[vv][0] = pk(a0, a1); xq[vv][1] = pk(a2, a3);
            }
            #pragma unroll
            for (int u = 0; u < 25; ++u) {
                const ull* rb = Rp + u * 28 + vg * 4;
                ulonglong2 ra = *reinterpret_cast<const ulonglong2*>(rb);
                ulonglong2 rc = *reinterpret_cast<const ulonglong2*>(rb + 2);
                acc[u][0] = f2fma(xq[0][0], ra.x, acc[u][0]);
                acc[u][1] = f2fma(xq[0][1], ra.x, acc[u][1]);
                acc[u][0] = f2fma(xq[1][0], ra.y, acc[u][0]);
                acc[u][1] = f2fma(xq[1][1], ra.y, acc[u][1]);
                acc[u][0] = f2fma(xq[2][0], rc.x, acc[u][0]);
                acc[u][1] = f2fma(xq[2][1], rc.x, acc[u][1]);
                acc[u][0] = f2fma(xq[3][0], rc.y, acc[u][0]);
                acc[u][1] = f2fma(xq[3][1], rc.y, acc[u][1]);
            }
        }
        // tail v = 24
        {
            float a0 = xs[tid * 25 + 24];
            float a1 = xs[(tid + 64) * 25 + 24];
            float a2 = xs[(tid + 128) * 25 + 24];
            float a3 = xs[(tid + 192) * 25 + 24];
            ull x0 = pk(a0, a1), x1 = pk(a2, a3);
            #pragma unroll
            for (int u = 0; u < 25; ++u) {
                ull rd = Rp[u * 28 + 24];
                acc[u][0] = f2fma(x0, rd, acc[u][0]);
                acc[u][1] = f2fma(x1, rd, acc[u][1]);
            }
        }
    }

    // unpack + thread-local stats + stage into xs
    float sum = 0.f, sq = 0.f;
    __syncthreads();
    #pragma unroll
    for (int u = 0; u < 25; ++u) {
        float z0, z1, z2, z3;
        upk(z0, z1, acc[u][0]);
        upk(z2, z3, acc[u][1]);
        xs[tid * 25 + u]         = z0;
        xs[(tid + 64) * 25 + u]  = z1;
        xs[(tid + 128) * 25 + u] = z2;
        xs[(tid + 192) * 25 + u] = z3;
        sum += z0 + z1 + z2 + z3;
        sq  = fmaf(z0, z0, sq); sq = fmaf(z1, z1, sq);
        sq  = fmaf(z2, z2, sq); sq = fmaf(z3, z3, sq);
    }
    rs[tid] = sum; rq[tid] = sq;
    __syncthreads();
    {
        float4* outp = reinterpret_cast<float4*>(ybuf + ((size_t)(n * O + o)) * 6400);
        const float4* sp = reinterpret_cast<const float4*>(xs);
        for (int i = tid; i < 1600; i += 64) outp[i] = sp[i];
    }
    for (int st = 32; st > 0; st >>= 1) {
        if (tid < st) { rs[tid] += rs[tid + st]; rq[tid] += rq[tid + st]; }
        __syncthreads();
    }
    if (tid == 0) g_part2[o * NB + n] = make_float2(rs[0], rq[0]);
}

// ---------------- K5: BN stats combine ----------------
__global__ void k_stats2(const float* __restrict__ bnw, const float* __restrict__ bnb)
{
    int o = threadIdx.x;
    float s = 0.f, s2 = 0.f;
    for (int nn = 0; nn < NB; ++nn) {
        float2 p = g_part2[o * NB + nn];
        s += p.x; s2 += p.y;
    }
    float M = (float)(NB * T * V);
    float mean = s / M;
    float var  = s2 / M - mean * mean;
    float sc = bnw[o] * rsqrtf(var + 1e-5f);
    g_stats[o] = make_float2(sc, bnb[o] - mean * sc);
}

// ---------------- K6: BN apply + residual + relu ----------------
__global__ void k_final(float4* __restrict__ ybuf, const float4* __restrict__ x)
{
    int idx = blockIdx.x * 256 + threadIdx.x;
    int o = (idx / (T * V / 4)) & 63;
    float2 ss = g_stats[o];
    float4 y = ybuf[idx], xx = x[idx];
    y.x = fmaxf(fmaf(y.x, ss.x, ss.y) + xx.x, 0.f);
    y.y = fmaxf(fmaf(y.y, ss.x, ss.y) + xx.y, 0.f);
    y.z = fmaxf(fmaf(y.z, ss.x, ss.y) + xx.z, 0.f);
    y.w = fmaxf(fmaf(y.w, ss.x, ss.y) + xx.w, 0.f);
    ybuf[idx] = y;
}

// ---------------- launch ----------------
extern "C" void kernel_launch(void* const* d_in, const int* in_sizes, int n_in,
                              void* d_out, int out_size)
{
    (void)in_sizes; (void)n_in; (void)out_size;
    const float* x    = (const float*)d_in[0];
    const float* A    = (const float*)d_in[1];
    const float* alph = (const float*)d_in[2];
    const float* w1   = (const float*)d_in[3];
    const float* b1   = (const float*)d_in[4];
    const float* w2   = (const float*)d_in[5];
    const float* b2   = (const float*)d_in[6];
    const float* w3   = (const float*)d_in[7];
    const float* b3   = (const float*)d_in[8];
    const float* w4   = (const float*)d_in[9];
    const float* b4   = (const float*)d_in[10];
    const float* pw1  = (const float*)d_in[11];
    const float* pb1  = (const float*)d_in[12];
    const float* pw2  = (const float*)d_in[13];
    const float* pb2  = (const float*)d_in[14];
    const float* dww  = (const float*)d_in[15];
    const float* pjw  = (const float*)d_in[16];
    const float* beta = (const float*)d_in[17];
    const float* gamma= (const float*)d_in[18];
    const float* bnw  = (const float*)d_in[19];
    const float* bnb  = (const float*)d_in[20];
    float* out = (float*)d_out;

    cudaFuncSetAttribute(k_R,   cudaFuncAttributeMaxDynamicSharedMemorySize, 15800 * 4);
    cudaFuncSetAttribute(k_x3m, cudaFuncAttributeMaxDynamicSharedMemorySize, SM_TOT);
    cudaFuncSetAttribute(k_y,   cudaFuncAttributeMaxDynamicSharedMemorySize, KY_SMEM_B);

    // order: slot 4 (profiled) = k_R; deps: k_x3m needs k_wb; k_R needs k_xm; k_y needs k_R + k_x3m
    k_xm<<<NB * C, 256>>>(x);
    k_wb<<<S * O * C / 256, 256>>>(w3);
    k_x3m<<<dim3(100, NB), 384, SM_TOT>>>(x, b3);
    k_R<<<dim3(NB, S), 512, 15800 * 4>>>(A, alph, w1, b1, w2, b2, w4, b4,
                                         pw1, pb1, pw2, pb2, dww, pjw, beta, gamma);
    k_y<<<dim3(O, NB), 64, KY_SMEM_B>>>(out);
    k_stats2<<<1, O>>>(bnw, bnb);
    k_final<<<(NB * C * T * V) / 1024, 256>>>((float4*)out, (const float4*)x);
}

// round 16
// speedup vs baseline: 1.1204x; 1.1204x over previous
#include <cuda_runtime.h>
#include <cuda_bf16.h>

#define NB 64
#define C  64
#define T  256
#define V  25
#define S  3
#define R  8
#define O  64

typedef unsigned long long ull;
typedef unsigned int u32;

// ---------------- scratch ----------------
__device__ float  g_xm[NB * C * V];
__device__ __nv_bfloat16 g_w3h[S * O * C];
__device__ __nv_bfloat16 g_w3l[S * O * C];
__device__ float  g_qa[(size_t)S * NB * R * V * V];      // qall staged for epilogue
__device__ float  g_ta[(size_t)S * NB * R * V * V];      // tanh-aux staged
__device__ float  g_R4[(size_t)S * NB * O * V * V];
__device__ float  g_x3[(size_t)S * NB * O * T * V];
__device__ float2 g_stats[O];
__device__ float2 g_part2[O * NB];

// ---------------- f32x2 helpers ----------------
__device__ __forceinline__ ull pk(float lo, float hi) {
    ull r; asm("mov.b64 %0, {%1,%2};" : "=l"(r) : "f"(lo), "f"(hi)); return r;
}
__device__ __forceinline__ void upk(float& lo, float& hi, ull v) {
    asm("mov.b64 {%0,%1}, %2;" : "=f"(lo), "=f"(hi) : "l"(v));
}
__device__ __forceinline__ ull f2fma(ull a, ull b, ull c) {
    ull d; asm("fma.rn.f32x2 %0, %1, %2, %3;" : "=l"(d) : "l"(a), "l"(b), "l"(c)); return d;
}

// ---------------- warp-MMA helpers ----------------
__device__ __forceinline__ u32 s2u(const void* p) {
    u32 a; asm("{ .reg .u64 t; cvta.to.shared.u64 t, %1; cvt.u32.u64 %0, t; }" : "=r"(a) : "l"(p));
    return a;
}
__device__ __forceinline__ u32 sw128(u32 b) { return b ^ ((b >> 3) & 0x70); }

__device__ __forceinline__ void ldsm_x4(u32* r, u32 addr) {
    asm volatile("ldmatrix.sync.aligned.m8n8.x4.shared.b16 {%0,%1,%2,%3}, [%4];"
        : "=r"(r[0]), "=r"(r[1]), "=r"(r[2]), "=r"(r[3]) : "r"(addr));
}
__device__ __forceinline__ void ldsm_x4_t(u32* r, u32 addr) {
    asm volatile("ldmatrix.sync.aligned.m8n8.x4.trans.shared.b16 {%0,%1,%2,%3}, [%4];"
        : "=r"(r[0]), "=r"(r[1]), "=r"(r[2]), "=r"(r[3]) : "r"(addr));
}
__device__ __forceinline__ void mma16816(float* d, const u32* a, u32 b0, u32 b1) {
    asm volatile(
        "mma.sync.aligned.m16n8k16.row.col.f32.bf16.bf16.f32 "
        "{%0,%1,%2,%3}, {%4,%5,%6,%7}, {%8,%9}, {%0,%1,%2,%3};"
        : "+f"(d[0]), "+f"(d[1]), "+f"(d[2]), "+f"(d[3])
        : "r"(a[0]), "r"(a[1]), "r"(a[2]), "r"(a[3]), "r"(b0), "r"(b1));
}

// ---------------- K0: w3 -> bf16 hi/lo ----------------
__global__ void k_wb(const float* __restrict__ w3g) {
    int i = blockIdx.x * 256 + threadIdx.x;
    float w = w3g[i];
    __nv_bfloat16 h = __float2bfloat16(w);
    g_w3h[i] = h;
    g_w3l[i] = __float2bfloat16(w - __bfloat162float(h));
}

// ---------------- K1: xm ----------------
__global__ void k_xm(const float* __restrict__ x) {
    __shared__ float red[256 * V];
    int bx  = blockIdx.x;
    int tid = threadIdx.x;
    const float* row = x + (size_t)bx * T * V + (size_t)tid * V;
    #pragma unroll
    for (int v = 0; v < V; ++v) red[tid * V + v] = row[v];
    __syncthreads();
    for (int st = 128; st > 0; st >>= 1) {
        if (tid < st) {
            #pragma unroll
            for (int v = 0; v < V; ++v) red[tid * V + v] += red[(tid + st) * V + v];
        }
        __syncthreads();
    }
    if (tid < V) g_xm[bx * V + tid] = red[tid] * (1.0f / T);
}

// ---------------- K2: x3 GEMM (R12 form, untouched) ----------------
constexpr int SM_AH = 0;
constexpr int SM_AL = 24576;
constexpr int SM_BH = 49152;
constexpr int SM_BL = 57344;
constexpr int SM_TOT = 65536;

__global__ void __launch_bounds__(384) k_x3m(const float* __restrict__ x,
                                             const float* __restrict__ b3g)
{
    extern __shared__ char smc[];
    int tid = threadIdx.x, wid = tid >> 5, lane = tid & 31;
    int n = blockIdx.y, tv0 = blockIdx.x * 64;

    for (int i = tid; i < 2 * 192 * 8; i += 384) {
        int half = i >= 1536;
        int j = half ? (i - 1536) : i;
        int row = j >> 3, off = (j & 7) * 16;
        const char* src = reinterpret_cast<const char*>(half ? g_w3l : g_w3h);
        uint4 v = *reinterpret_cast<const uint4*>(src + row * 128 + off);
        *reinterpret_cast<uint4*>(smc + (half ? SM_AL : SM_AH) + sw128(row * 128 + off)) = v;
    }
    for (int i = tid; i < 64 * 32; i += 384) {
        int c = i >> 5, j2 = i & 31;
        float2 v = *reinterpret_cast<const float2*>(
            x + ((size_t)(n * C + c)) * 6400 + tv0 + j2 * 2);
        __nv_bfloat16 h0 = __float2bfloat16(v.x), h1 = __float2bfloat16(v.y);
        __nv_bfloat16 l0 = __float2bfloat16(v.x - __bfloat162float(h0));
        __nv_bfloat16 l1 = __float2bfloat16(v.y - __bfloat162float(h1));
        u32 off = sw128((u32)(c * 128 + j2 * 4));
        *reinterpret_cast<__nv_bfloat162*>(smc + SM_BH + off) = __nv_bfloat162(h0, h1);
        *reinterpret_cast<__nv_bfloat162*>(smc + SM_BL + off) = __nv_bfloat162(l0, l1);
    }
    __syncthreads();

    u32 sah = s2u(smc + SM_AH), sal = s2u(smc + SM_AL);
    u32 sbh = s2u(smc + SM_BH), sbl = s2u(smc + SM_BL);
    int gid = lane >> 2, tig = lane & 3;
    int m0 = wid * 16;

    float acc[8][4];
    #pragma unroll
    for (int j = 0; j < 8; ++j)
        #pragma unroll
        for (int q = 0; q < 4; ++q) acc[j][q] = 0.f;

    #pragma unroll
    for (int k0 = 0; k0 < 64; k0 += 16) {
        u32 arow = sw128((m0 + (lane & 15)) * 128 + (lane >> 4) * 16 + k0 * 2);
        u32 ah[4], al[4];
        ldsm_x4(ah, sah + arow);
        ldsm_x4(al, sal + arow);
        int krow = k0 + (lane & 7) + ((lane >> 3) & 1) * 8;
        u32 bh[4][4], bl[4][4];
        #pragma unroll
        for (int nt = 0; nt < 4; ++nt) {
            u32 boff = sw128(krow * 128 + nt * 32 + (lane >> 4) * 16);
            ldsm_x4_t(bh[nt], sbh + boff);
            ldsm_x4_t(bl[nt], sbl + boff);
        }
        #pragma unroll
        for (int nt = 0; nt < 4; ++nt) {
            mma16816(acc[2 * nt],     ah, bh[nt][0], bh[nt][1]);
            mma16816(acc[2 * nt + 1], ah, bh[nt][2], bh[nt][3]);
            mma16816(acc[2 * nt],     ah, bl[nt][0], bl[nt][1]);
            mma16816(acc[2 * nt + 1], ah, bl[nt][2], bl[nt][3]);
            mma16816(acc[2 * nt],     al, bh[nt][0], bh[nt][1]);
            mma16816(acc[2 * nt + 1], al, bh[nt][2], bh[nt][3]);
        }
    }

    int s = wid >> 2;
    int o0 = (wid & 3) * 16 + gid;
    float bias0 = b3g[s * O + o0];
    float bias1 = b3g[s * O + o0 + 8];
    float* d0 = g_x3 + (((size_t)s * NB + n) * O + o0) * 6400 + tv0;
    float* d1 = d0 + (size_t)8 * 6400;
    #pragma unroll
    for (int j = 0; j < 8; ++j) {
        int col = j * 8 + 2 * tig;
        *reinterpret_cast<float2*>(d0 + col) =
            make_float2(acc[j][0] + bias0, acc[j][1] + bias0);
        *reinterpret_cast<float2*>(d1 + col) =
            make_float2(acc[j][2] + bias1, acc[j][3] + bias1);
    }
}

// ---------------- K3: k_R main (qas/ta only; epilogue split off) ----------------
__global__ void k_R(const float* __restrict__ alphag,
                    const float* __restrict__ w1g,  const float* __restrict__ b1g,
                    const float* __restrict__ w2g,  const float* __restrict__ b2g,
                    const float* __restrict__ pw1g, const float* __restrict__ pb1g,
                    const float* __restrict__ pw2g, const float* __restrict__ pb2g,
                    const float* __restrict__ dwwg, const float* __restrict__ gammag)
{
    extern __shared__ float sm[];
    float* q1s = sm;            // 5000 (reused as ta)
    float* qas = sm + 5000;     // 5000
    float* ds  = sm + 10000;    // 5000
    float* x1s = sm + 15000;    // 200
    float* x2s = sm + 15200;    // 200
    float* as_ = sm + 15400;    // 200
    float* bs_ = sm + 15600;    // 200

    int n = blockIdx.x, s = blockIdx.y;
    int tid = threadIdx.x;
    const float* xm = g_xm + n * (C * V);

    for (int idx = tid; idx < R * V; idx += blockDim.x) {
        int r = idx / V, u = idx % V;
        float s1 = b1g[s * R + r], s2 = b2g[s * R + r];
        const float* w1r = w1g + (s * R + r) * C;
        const float* w2r = w2g + (s * R + r) * C;
        for (int c = 0; c < C; ++c) {
            float xv = xm[c * V + u];
            s1 = fmaf(w1r[c], xv, s1);
            s2 = fmaf(w2r[c], xv, s2);
        }
        x1s[idx] = s1; x2s[idx] = s2;
    }
    __syncthreads();
    for (int idx = tid; idx < R * V; idx += blockDim.x) {
        int r = idx / V, u = idx % V;
        const float* p1 = pw1g + (s * R + r) * (2 * R);
        float av = 0.f, bv = 0.f;
        #pragma unroll
        for (int p = 0; p < R; ++p) {
            av = fmaf(p1[p],     x2s[p * V + u], av);
            bv = fmaf(p1[R + p], x2s[p * V + u], bv);
        }
        as_[idx] = av; bs_[idx] = bv;
    }
    __syncthreads();
    for (int idx = tid; idx < R * V * V; idx += blockDim.x) {
        int r = idx / (V * V), uv = idx % (V * V), u = uv / V, v = uv % V;
        q1s[idx] = tanhf(x1s[r * V + u] - x2s[r * V + v]);
    }
    __syncthreads();
    float gma = gammag[s];
    for (int uv = tid; uv < V * V; uv += blockDim.x) {
        int u = uv / V, v = uv % V;
        float h[R];
        #pragma unroll
        for (int p = 0; p < R; ++p)
            h[p] = fmaxf(as_[p * V + u] + bs_[p * V + v] + pb1g[s * R + p], 0.f);
        #pragma unroll
        for (int r = 0; r < R; ++r) {
            float q2 = pb2g[s * R + r];
            const float* p2 = pw2g + (s * R + r) * R;
            #pragma unroll
            for (int p = 0; p < R; ++p) q2 = fmaf(p2[p], h[p], q2);
            qas[r * V * V + uv] = q1s[r * V * V + uv] + gma * q2;
        }
    }
    __syncthreads();
    for (int idx = tid; idx < R * V * V; idx += blockDim.x) {
        int r = idx / (V * V), uv = idx % (V * V), u = uv / V, v = uv % V;
        const float* kw = dwwg + (s * R + r) * 9;
        float acc = 0.f;
        #pragma unroll
        for (int ki = 0; ki < 3; ++ki) {
            int uu = u + ki - 1; if (uu < 0 || uu >= V) continue;
            #pragma unroll
            for (int kj = 0; kj < 3; ++kj) {
                int vv = v + kj - 1; if (vv < 0 || vv >= V) continue;
                acc = fmaf(q1s[r * V * V + uu * V + vv], kw[ki * 3 + kj], acc);
            }
        }
        ds[idx] = acc;
    }
    __syncthreads();
    for (int idx = tid; idx < R * V * V; idx += blockDim.x) {
        int r = idx / (V * V), uv = idx % (V * V), u = uv / V, v = uv % V;
        float acc = 0.f;
        for (int ki = -1; ki <= 1; ++ki) {
            int uu = u + ki; if (uu < 0 || uu >= V) continue;
            for (int kj = -1; kj <= 1; ++kj) {
                int vv = v + kj; if (vv < 0 || vv >= V) continue;
                acc += ds[r * V * V + uu * V + vv];
            }
        }
        q1s[idx] = tanhf(acc * (1.f / 9.f));
    }
    __syncthreads();
    // write qas + ta to global for the epilogue kernel
    float* qa = g_qa + ((size_t)(s * NB + n)) * 5000;
    float* ta = g_ta + ((size_t)(s * NB + n)) * 5000;
    for (int idx = tid; idx < 5000; idx += blockDim.x) {
        qa[idx] = qas[idx];
        ta[idx] = q1s[idx];
    }
}

// ---------------- K3b: R epilogue, high occupancy, no div/mod ----------------
__global__ void __launch_bounds__(256) k_Re(const float* __restrict__ Ag,
                                            const float* __restrict__ alphag,
                                            const float* __restrict__ w4g,
                                            const float* __restrict__ b4g,
                                            const float* __restrict__ pjwg,
                                            const float* __restrict__ betag)
{
    int n = blockIdx.x, s = blockIdx.y, och = blockIdx.z;   // 16 o per block
    int tid = threadIdx.x;
    const float* qa = g_qa + ((size_t)(s * NB + n)) * 5000;
    const float* ta = g_ta + ((size_t)(s * NB + n)) * 5000;
    const float* Ab = Ag + s * 625;
    float alpha = alphag[0], beta = betag[s];
    float* dst = g_R4 + ((size_t)(s * NB + n)) * O * 625;

    #pragma unroll 1
    for (int oi = 0; oi < 16; ++oi) {
        int o = och * 16 + oi;
        float w4r[R], pjr[R];
        #pragma unroll
        for (int r = 0; r < R; ++r) {
            w4r[r] = w4g[(s * O + o) * R + r];
            pjr[r] = pjwg[(s * O + o) * R + r];
        }
        float b4v = b4g[s * O + o];
        for (int uv = tid; uv < 625; uv += 256) {
            float a1 = b4v, a2 = 0.f;
            #pragma unroll
            for (int r = 0; r < R; ++r) {
                a1 = fmaf(w4r[r], qa[r * 625 + uv], a1);
                a2 = fmaf(pjr[r], ta[r * 625 + uv], a2);
            }
            dst[o * 625 + uv] = fmaf(alpha, a1, Ab[uv]) + beta * a2;
        }
    }
}

// ---------------- K4: y (exact R12 winner) ----------------
constexpr int KY_SMEM_B = (6400 + 2100 + 128) * 4;     // 34512

__global__ void __launch_bounds__(64) k_y(float* __restrict__ ybuf)
{
    extern __shared__ float smf[];
    float* xs  = smf;            // 6400
    float* Rs4 = smf + 6400;     // 2100
    float* rs  = smf + 8500;     // 64
    float* rq  = smf + 8564;     // 64
    int n = blockIdx.y, o = blockIdx.x;
    int tid = threadIdx.x;

    for (int i = tid; i < S * 25 * 28; i += 64) {
        int s = i / 700, rem = i % 700, u = rem / 28, j = rem % 28;
        Rs4[i] = (j < 25) ? g_R4[(((size_t)s * NB + n) * O + o) * 625 + u * 25 + j] : 0.f;
    }

    ull acc[25][2];
    #pragma unroll
    for (int u = 0; u < 25; ++u) { acc[u][0] = 0ull; acc[u][1] = 0ull; }

    #pragma unroll 1
    for (int s = 0; s < S; ++s) {
        __syncthreads();
        {
            const float4* src = reinterpret_cast<const float4*>(
                g_x3 + (((size_t)(s * NB + n)) * O + o) * 6400);
            float4* dst = reinterpret_cast<float4*>(xs);
            for (int i = tid; i < 1600; i += 64) dst[i] = src[i];
        }
        __syncthreads();
        const float* Rp = Rs4 + s * 700;
        #pragma unroll 1
        for (int vg = 0; vg < 6; ++vg) {
            ull xq[4][2];
            #pragma unroll
            for (int vv = 0; vv < 4; ++vv) {
                int v = vg * 4 + vv;
                float a0 = xs[tid * 25 + v];
                float a1 = xs[(tid + 64) * 25 + v];
                float a2 = xs[(tid + 128) * 25 + v];
                float a3 = xs[(tid + 192) * 25 + v];
                xq[vv][0] = pk(a0, a1); xq[vv][1] = pk(a2, a3);
            }
            #pragma unroll
            for (int u = 0; u < 25; ++u) {
                float4 rf = *reinterpret_cast<const float4*>(Rp + u * 28 + vg * 4);
                ull rd;
                rd = pk(rf.x, rf.x);
                acc[u][0] = f2fma(xq[0][0], rd, acc[u][0]);
                acc[u][1] = f2fma(xq[0][1], rd, acc[u][1]);
                rd = pk(rf.y, rf.y);
                acc[u][0] = f2fma(xq[1][0], rd, acc[u][0]);
                acc[u][1] = f2fma(xq[1][1], rd, acc[u][1]);
                rd = pk(rf.z, rf.z);
                acc[u][0] = f2fma(xq[2][0], rd, acc[u][0]);
                acc[u][1] = f2fma(xq[2][1], rd, acc[u][1]);
                rd = pk(rf.w, rf.w);
                acc[u][0] = f2fma(xq[3][0], rd, acc[u][0]);
                acc[u][1] = f2fma(xq[3][1], rd, acc[u][1]);
            }
        }
        {
            float a0 = xs[tid * 25 + 24];
            float a1 = xs[(tid + 64) * 25 + 24];
            float a2 = xs[(tid + 128) * 25 + 24];
            float a3 = xs[(tid + 192) * 25 + 24];
            ull x0 = pk(a0, a1), x1 = pk(a2, a3);
            #pragma unroll
            for (int u = 0; u < 25; ++u) {
                float rv = Rp[u * 28 + 24];
                ull rd = pk(rv, rv);
                acc[u][0] = f2fma(x0, rd, acc[u][0]);
                acc[u][1] = f2fma(x1, rd, acc[u][1]);
            }
        }
    }

    float sum = 0.f, sq = 0.f;
    __syncthreads();
    #pragma unroll
    for (int u = 0; u < 25; ++u) {
        float z0, z1, z2, z3;
        upk(z0, z1, acc[u][0]);
        upk(z2, z3, acc[u][1]);
        xs[tid * 25 + u]         = z0;
        xs[(tid + 64) * 25 + u]  = z1;
        xs[(tid + 128) * 25 + u] = z2;
        xs[(tid + 192) * 25 + u] = z3;
        sum += z0 + z1 + z2 + z3;
        sq  = fmaf(z0, z0, sq); sq = fmaf(z1, z1, sq);
        sq  = fmaf(z2, z2, sq); sq = fmaf(z3, z3, sq);
    }
    rs[tid] = sum; rq[tid] = sq;
    __syncthreads();
    {
        float4* outp = reinterpret_cast<float4*>(ybuf + ((size_t)(n * O + o)) * 6400);
        const float4* sp = reinterpret_cast<const float4*>(xs);
        for (int i = tid; i < 1600; i += 64) outp[i] = sp[i];
    }
    for (int st = 32; st > 0; st >>= 1) {
        if (tid < st) { rs[tid] += rs[tid + st]; rq[tid] += rq[tid + st]; }
        __syncthreads();
    }
    if (tid == 0) g_part2[o * NB + n] = make_float2(rs[0], rq[0]);
}

// ---------------- K5: BN stats combine ----------------
__global__ void k_stats2(const float* __restrict__ bnw, const float* __restrict__ bnb)
{
    int o = threadIdx.x;
    float s = 0.f, s2 = 0.f;
    for (int nn = 0; nn < NB; ++nn) {
        float2 p = g_part2[o * NB + nn];
        s += p.x; s2 += p.y;
    }
    float M = (float)(NB * T * V);
    float mean = s / M;
    float var  = s2 / M - mean * mean;
    float sc = bnw[o] * rsqrtf(var + 1e-5f);
    g_stats[o] = make_float2(sc, bnb[o] - mean * sc);
}

// ---------------- K6: BN apply + residual + relu ----------------
__global__ void k_final(float4* __restrict__ ybuf, const float4* __restrict__ x)
{
    int idx = blockIdx.x * 256 + threadIdx.x;
    int o = (idx / (T * V / 4)) & 63;
    float2 ss = g_stats[o];
    float4 y = ybuf[idx], xx = x[idx];
    y.x = fmaxf(fmaf(y.x, ss.x, ss.y) + xx.x, 0.f);
    y.y = fmaxf(fmaf(y.y, ss.x, ss.y) + xx.y, 0.f);
    y.z = fmaxf(fmaf(y.z, ss.x, ss.y) + xx.z, 0.f);
    y.w = fmaxf(fmaf(y.w, ss.x, ss.y) + xx.w, 0.f);
    ybuf[idx] = y;
}

// ---------------- launch ----------------
extern "C" void kernel_launch(void* const* d_in, const int* in_sizes, int n_in,
                              void* d_out, int out_size)
{
    (void)in_sizes; (void)n_in; (void)out_size;
    const float* x    = (const float*)d_in[0];
    const float* A    = (const float*)d_in[1];
    const float* alph = (const float*)d_in[2];
    const float* w1   = (const float*)d_in[3];
    const float* b1   = (const float*)d_in[4];
    const float* w2   = (const float*)d_in[5];
    const float* b2   = (const float*)d_in[6];
    const float* w3   = (const float*)d_in[7];
    const float* b3   = (const float*)d_in[8];
    const float* w4   = (const float*)d_in[9];
    const float* b4   = (const float*)d_in[10];
    const float* pw1  = (const float*)d_in[11];
    const float* pb1  = (const float*)d_in[12];
    const float* pw2  = (const float*)d_in[13];
    const float* pb2  = (const float*)d_in[14];
    const float* dww  = (const float*)d_in[15];
    const float* pjw  = (const float*)d_in[16];
    const float* beta = (const float*)d_in[17];
    const float* gamma= (const float*)d_in[18];
    const float* bnw  = (const float*)d_in[19];
    const float* bnb  = (const float*)d_in[20];
    float* out = (float*)d_out;

    cudaFuncSetAttribute(k_R,   cudaFuncAttributeMaxDynamicSharedMemorySize, 15800 * 4);
    cudaFuncSetAttribute(k_x3m, cudaFuncAttributeMaxDynamicSharedMemorySize, SM_TOT);
    cudaFuncSetAttribute(k_y,   cudaFuncAttributeMaxDynamicSharedMemorySize, KY_SMEM_B);

    k_xm<<<NB * C, 256>>>(x);
    k_wb<<<S * O * C / 256, 256>>>(w3);
    k_x3m<<<dim3(100, NB), 384, SM_TOT>>>(x, b3);
    k_R<<<dim3(NB, S), 512, 15800 * 4>>>(alph, w1, b1, w2, b2,
                                         pw1, pb1, pw2, pb2, dww, gamma);
    k_Re<<<dim3(NB, S, 4), 256>>>(A, alph, w4, b4, pjw, beta);
    k_y<<<dim3(O, NB), 64, KY_SMEM_B>>>(out);
    k_stats2<<<1, O>>>(bnw, bnb);
    k_final<<<(NB * C * T * V) / 1024, 256>>>((float4*)out, (const float4*)x);
}